// round 9
// baseline (speedup 1.0000x reference)
#include <cuda_runtime.h>
#include <cuda_bf16.h>

#define IW 1280
#define IH 720
#define IB 32

#define SEGW  256                   // pixels per CTA segment
#define NSEG  (IW / SEGW)           // 5 segments per row
#define HALOL 68                    // left halo floats (covers x0 >= xs-65)
#define ROWF  (HALOL + SEGW + 4)    // 328 floats = 1312 B per CTA
#define NSLOT (ROWF / 4)            // 82 float4 slots

__global__ __launch_bounds__(64) void warp_disp_seg(
    const float* __restrict__ img,
    const float* __restrict__ disp,
    float* __restrict__ out)
{
    __shared__ float sm[ROWF];

    const int t    = threadIdx.x;             // 64 threads, 4 px each
    const int blk  = blockIdx.x;              // = rowi * NSEG + segx
    const int segx = blk % NSEG;
    const int rowi = blk / NSEG;              // = b*IH + y
    const int y    = rowi % IH;
    const int b    = rowi / IH;
    const int xs   = segx * SEGW;

    // ---- vertical terms (uniform per CTA): iy = y*H/(H-1) - 0.5 ----
    float iy  = fmaf((float)y, (float)IH / (float)(IH - 1), -0.5f);
    float y0f = floorf(iy);
    float wy1 = iy - y0f;
    float wy0 = 1.0f - wy1;
    int   y0  = (int)y0f;
    int   y1  = y0 + 1;
    bool  vy0 = (unsigned)y0 < (unsigned)IH;
    bool  vy1 = (unsigned)y1 < (unsigned)IH;

    const float* imgb = img + (size_t)b * (IH * IW);
    const float* r0p  = imgb + (vy0 ? y0 : 0) * IW;
    const float* r1p  = imgb + (vy1 ? y1 : 0) * IW;

    // disp prefetch (consumed after the barrier)
    const int p = rowi * IW + xs + t * 4;
    float4 d4 = *reinterpret_cast<const float4*>(disp + p);

    // ---- stage h window [xs-68, xs+260): 82 float4 slots over 64 threads ----
    const float4 z4 = make_float4(0.f, 0.f, 0.f, 0.f);
#pragma unroll
    for (int ld = 0; ld < 2; ld++) {
        int s = t + ld * 64;
        if (ld == 0 || t < (NSLOT - 64)) {
            int gx = xs - HALOL + s * 4;                  // multiple of 4
            bool vx = (unsigned)gx <= (unsigned)(IW - 4); // fully-inside float4
            float4 a0 = (vx && vy0) ? *reinterpret_cast<const float4*>(r0p + gx) : z4;
            float4 a1 = (vx && vy1) ? *reinterpret_cast<const float4*>(r1p + gx) : z4;
            float4 h;
            h.x = fmaf(wy0, a0.x, wy1 * a1.x);
            h.y = fmaf(wy0, a0.y, wy1 * a1.y);
            h.z = fmaf(wy0, a0.z, wy1 * a1.z);
            h.w = fmaf(wy0, a0.w, wy1 * a1.w);
            *reinterpret_cast<float4*>(sm + s * 4) = h;
        }
    }
    __syncthreads();                                      // 2-warp barrier

    // ---- per pixel: 2 scalar LDS + horizontal lerp ----
    const float Ax = (float)IW / (float)(IW - 1);
    const float* sp = sm + HALOL;            // sp[x0 - xs] valid for x0 in [xs-65, xs+256]
    float dv[4] = {d4.x, d4.y, d4.z, d4.w};
    float res[4];
    const int xb = xs + t * 4;

#pragma unroll
    for (int i = 0; i < 4; i++) {
        float u   = (float)(xb + i) - dv[i];
        float ix  = fmaf(u, Ax, -0.5f);
        float x0f = floorf(ix);
        float wx1 = ix - x0f;
        float wx0 = 1.0f - wx1;
        int   xr  = (int)x0f - xs;           // in [-65, 255]
        float v0 = sp[xr];
        float v1 = sp[xr + 1];
        res[i] = fmaf(v1, wx1, v0 * wx0);
    }

    *reinterpret_cast<float4*>(out + p) = make_float4(res[0], res[1], res[2], res[3]);
}

extern "C" void kernel_launch(void* const* d_in, const int* in_sizes, int n_in,
                              void* d_out, int out_size)
{
    const float* right_img = (const float*)d_in[0];
    const float* disp      = (const float*)d_in[1];
    float*       out       = (float*)d_out;

    const int blocks = IB * IH * NSEG;       // 115200 CTAs of 64 threads
    warp_disp_seg<<<blocks, 64>>>(right_img, disp, out);
}

// round 13
// speedup vs baseline: 1.0893x; 1.0893x over previous
#include <cuda_runtime.h>
#include <cuda_bf16.h>

#define IW 1280
#define IH 720
#define IB 32
#define WPC 8                    // warps per CTA
#define NCH 10                   // 128-px chunks per row
#define RING 512                 // floats per warp ring (4 chunk slots)

// slot of chunk c = ((c+1)&3)*128 ; h[x] lives at ring[(x+128)&511]

__global__ __launch_bounds__(WPC * 32) void warp_disp_ring(
    const float* __restrict__ img,
    const float* __restrict__ disp,
    float* __restrict__ out)
{
    __shared__ float ring[WPC][RING];

    const int w    = threadIdx.x >> 5;
    const int lane = threadIdx.x & 31;
    const int l4   = lane * 4;
    const int rowi = blockIdx.x * WPC + w;     // = b*IH + y
    const int y    = rowi % IH;
    const int b    = rowi / IH;
    float* rg = ring[w];

    // ---- vertical terms (uniform per warp): iy = y*H/(H-1) - 0.5 ----
    float iy  = fmaf((float)y, (float)IH / (float)(IH - 1), -0.5f);
    float y0f = floorf(iy);
    float wy1 = iy - y0f;
    float wy0 = 1.0f - wy1;
    int   y0  = (int)y0f;
    int   y1  = y0 + 1;
    bool  vy0 = (unsigned)y0 < (unsigned)IH;
    bool  vy1 = (unsigned)y1 < (unsigned)IH;

    const float* imgb = img + (size_t)b * (IH * IW);
    const float* r0p  = imgb + (vy0 ? y0 : 0) * IW;
    const float* r1p  = imgb + (vy1 ? y1 : 0) * IW;
    const float* dsp  = disp + (size_t)rowi * IW;
    float*       op   = out  + (size_t)rowi * IW;

    const float4 z4 = make_float4(0.f, 0.f, 0.f, 0.f);
    const float  Ax = (float)IW / (float)(IW - 1);

    // ---- prologue ----
    // chunk -1 = zeros (slot 0)
    *reinterpret_cast<float4*>(rg + l4) = z4;
    // chunk 0 loads
    float4 a0 = vy0 ? *reinterpret_cast<const float4*>(r0p + l4) : z4;
    float4 a1 = vy1 ? *reinterpret_cast<const float4*>(r1p + l4) : z4;
    // chunk 1 loads (pipeline register B)
    float4 b0 = vy0 ? *reinterpret_cast<const float4*>(r0p + 128 + l4) : z4;
    float4 b1 = vy1 ? *reinterpret_cast<const float4*>(r1p + 128 + l4) : z4;
    // store chunk 0 (slot 1)
    {
        float4 h;
        h.x = fmaf(wy0, a0.x, wy1 * a1.x);
        h.y = fmaf(wy0, a0.y, wy1 * a1.y);
        h.z = fmaf(wy0, a0.z, wy1 * a1.z);
        h.w = fmaf(wy0, a0.w, wy1 * a1.w);
        *reinterpret_cast<float4*>(rg + 128 + l4) = h;
    }
    __syncwarp();

    // ---- main loop: iteration s loads chunk s+2, stores chunk s+1, gathers s ----
#pragma unroll
    for (int s = 0; s < NCH; s++) {
        const int c = s + 2;
        float4 A0 = z4, A1 = z4;
        if (c < NCH) {
            if (vy0) A0 = *reinterpret_cast<const float4*>(r0p + c * 128 + l4);
            if (vy1) A1 = *reinterpret_cast<const float4*>(r1p + c * 128 + l4);
        }
        float4 d4 = *reinterpret_cast<const float4*>(dsp + s * 128 + l4);

        // store chunk s+1 from B at slot ((s+2)&3)*128
        float4 h;
        h.x = fmaf(wy0, b0.x, wy1 * b1.x);
        h.y = fmaf(wy0, b0.y, wy1 * b1.y);
        h.z = fmaf(wy0, b0.z, wy1 * b1.z);
        h.w = fmaf(wy0, b0.w, wy1 * b1.w);
        *reinterpret_cast<float4*>(rg + ((s + 2) & 3) * 128 + l4) = h;
        __syncwarp();

        // gather step s: taps span [s*128-65, s*128+128] -> chunks s-1, s, s+1
        const int xb = s * 128 + l4;
        float dv[4] = {d4.x, d4.y, d4.z, d4.w};
        float res[4];
#pragma unroll
        for (int i = 0; i < 4; i++) {
            float u   = (float)(xb + i) - dv[i];
            float ix  = fmaf(u, Ax, -0.5f);
            float x0f = floorf(ix);
            float wx1 = ix - x0f;
            float wx0 = 1.0f - wx1;
            int   x0  = (int)x0f;               // >= xb-65 >= -65
            float v0 = rg[(x0 + 128) & (RING - 1)];
            float v1 = rg[(x0 + 129) & (RING - 1)];
            res[i] = fmaf(v1, wx1, v0 * wx0);
        }
        *reinterpret_cast<float4*>(op + s * 128 + l4) =
            make_float4(res[0], res[1], res[2], res[3]);

        b0 = A0; b1 = A1;
    }
}

extern "C" void kernel_launch(void* const* d_in, const int* in_sizes, int n_in,
                              void* d_out, int out_size)
{
    const float* right_img = (const float*)d_in[0];
    const float* disp      = (const float*)d_in[1];
    float*       out       = (float*)d_out;

    const int blocks = IB * IH / WPC;           // 2880 CTAs, 8 row-warps each
    warp_disp_ring<<<blocks, WPC * 32>>>(right_img, disp, out);
}